// round 14
// baseline (speedup 1.0000x reference)
#include <cuda_runtime.h>
#include <cuda_bf16.h>

#define NN 20000
#define EE 640000

// ----------------------------- device scratch -------------------------------
__device__ __align__(16) float g_A[NN * 64];
__device__ __align__(16) float g_B[NN * 64];
__device__ __align__(16) float g_U[NN * 64];
__device__ __align__(16) float g_V[NN * 64];
__device__ int g_deg[NN];
__device__ int g_cursor[NN];
__device__ int g_rowptr[NN + 1];
__device__ int g_csr[EE];
__device__ int g_bsum[32];
__device__ int g_barcnt[4];
__device__ int g_is64;
__device__ float g_T[81 * 64];
__device__ float g_Tb[9 * 64];
__device__ float g_G[25 * 49];
__device__ float g_Bias[25];

// edge fetch helpers (dtype-agnostic: int32 or int64 edge_index)
__device__ __forceinline__ int edge_src(const int* w, int e) {
    if (g_is64) return (int)((const long long*)w)[e];
    return w[e];
}
__device__ __forceinline__ int edge_dst(const int* w, int e) {
    if (g_is64) return (int)((const long long*)w)[EE + e];
    return w[EE + e];
}

// ----------------------------- GEMM core (shared) ----------------------------
template <int DIN, int DOUT, int RT, int XS>
__device__ __forceinline__ void gemm_from_smem(
    const float (*sX)[XS], unsigned long long (*sW)[DOUT + 2],
    const float* __restrict__ Wl, const float* __restrict__ Wr,
    const float* __restrict__ bl,
    float* __restrict__ U, float* __restrict__ Vout, int n0, int tid) {
    const int ODIV = DOUT / 4;
    const int RPT = RT * ODIV / 256;
    const int KT = 32;
    int o_t = tid % ODIV, r_t = tid / ODIV;
    int r0 = r_t * RPT;

    unsigned long long acc[RPT * 4];
    #pragma unroll
    for (int c = 0; c < RPT * 4; c++) acc[c] = 0ull;

    for (int kt = 0; kt < DIN; kt += KT) {
        for (int id = tid; id < KT * DOUT; id += 256) {
            int k = id % KT, o = id / KT;
            float wl_ = Wl[(size_t)o * DIN + kt + k];
            float wr_ = Wr[(size_t)o * DIN + kt + k];
            *(float2*)&sW[k][o] = make_float2(wl_, wr_);
        }
        __syncthreads();
        #pragma unroll
        for (int k = 0; k < KT; k++) {
            unsigned long long w[4];
            #pragma unroll
            for (int j = 0; j < 4; j++) w[j] = sW[k][o_t + j * ODIV];
            #pragma unroll
            for (int i = 0; i < RPT; i++) {
                unsigned xu = __float_as_uint(sX[r0 + i][kt + k]);
                unsigned long long x2;
                asm("mov.b64 %0, {%1, %1};" : "=l"(x2) : "r"(xu));
                #pragma unroll
                for (int j = 0; j < 4; j++)
                    asm("fma.rn.f32x2 %0, %1, %2, %0;"
                        : "+l"(acc[i * 4 + j]) : "l"(x2), "l"(w[j]));
            }
        }
        __syncthreads();
    }

    #pragma unroll
    for (int i = 0; i < RPT; i++) {
        int row = n0 + r0 + i;
        if (row < NN) {
            #pragma unroll
            for (int j = 0; j < 4; j++) {
                unsigned lo, hi;
                asm("mov.b64 {%0, %1}, %2;" : "=r"(lo), "=r"(hi) : "l"(acc[i * 4 + j]));
                int o = o_t + j * ODIV;
                U[(size_t)row * DOUT + o] = __uint_as_float(lo);
                Vout[(size_t)row * DOUT + o] = __uint_as_float(hi) + __ldg(&bl[o]);
            }
        }
    }
}

// ----------------------------- pre GEMM --------------------------------------
template <int DIN, int DOUT>
__global__ void __launch_bounds__(256) k_pre(const float* __restrict__ xin,
                      const float* __restrict__ Wl, const float* __restrict__ Wr,
                      const float* __restrict__ bl,
                      float* __restrict__ U, float* __restrict__ Vout) {
    int tid = threadIdx.x;
    const int RT = 64;
    const int XS = DIN + 4;
    __shared__ float sX[RT][XS];
    __shared__ unsigned long long sW[32][DOUT + 2];
    int n0 = blockIdx.x * RT;
    for (int id = tid; id < RT * DIN; id += 256) {
        int k = id % DIN, r = id / DIN;
        int gr = n0 + r;
        sX[r][k] = (gr < NN) ? xin[(size_t)gr * DIN + k] : 0.f;
    }
    __syncthreads();
    gemm_from_smem<DIN, DOUT, RT, XS>(sX, sW, Wl, Wr, bl, U, Vout, n0, tid);
}

// ----------------------------- CSR build ------------------------------------
__global__ void k_zero(const int* __restrict__ w) {
    int i = blockIdx.x * 256 + threadIdx.x;
    if (i < NN) { g_deg[i] = 0; g_cursor[i] = 0; }
    if (i == 0) {
        int all0 = 1;
        for (int j = 0; j < 64; j++)
            if (w[2 * j + 1] != 0) { all0 = 0; break; }
        g_is64 = all0;
    }
}

__global__ void k_hist(const int* __restrict__ ei) {
    int e = blockIdx.x * 256 + threadIdx.x;
    if (e < EE) {
        int d = edge_dst(ei, e);
        if ((unsigned)d < NN) atomicAdd(&g_deg[d], 1);
    }
}

// fused scanA + scanC: 20 co-resident blocks with spin barrier (R7-validated)
__global__ void __launch_bounds__(1024) k_scan2() {
    __shared__ int ws[32];
    __shared__ int soff;
    int tid = threadIdx.x, lane = tid & 31, wid = tid >> 5;
    int bid = blockIdx.x;
    int i = bid * 1024 + tid;
    int v = (i < NN) ? g_deg[i] : 0;
    int x = v;
    #pragma unroll
    for (int off = 1; off < 32; off <<= 1) {
        int n = __shfl_up_sync(0xffffffffu, x, off);
        if (lane >= off) x += n;
    }
    if (lane == 31) ws[wid] = x;
    __syncthreads();
    if (wid == 0) {
        int w = ws[lane];
        #pragma unroll
        for (int off = 1; off < 32; off <<= 1) {
            int n = __shfl_up_sync(0xffffffffu, w, off);
            if (lane >= off) w += n;
        }
        ws[lane] = w;
    }
    __syncthreads();
    int incl = x + (wid ? ws[wid - 1] : 0);
    if (tid == 1023) g_bsum[bid] = incl;

    // grid barrier (all 20 blocks resident)
    __syncthreads();
    if (tid == 0) {
        __threadfence();
        atomicAdd(&g_barcnt[0], 1);
        while (atomicAdd(&g_barcnt[0], 0) < 20) __nanosleep(64);
    }
    __syncthreads();

    // per-block redundant offset scan of 20 partials
    if (tid < 32) {
        int vv = (tid < 20) ? __ldcg(&g_bsum[tid]) : 0;
        int xx = vv;
        #pragma unroll
        for (int off = 1; off < 32; off <<= 1) {
            int n = __shfl_up_sync(0xffffffffu, xx, off);
            if (tid >= off) xx += n;
        }
        if (tid == bid) soff = xx - vv;
    }
    __syncthreads();
    if (i < NN) g_rowptr[i + 1] = incl + soff;
    if (i == 0) g_rowptr[0] = 0;

    // reset barrier state for next graph replay
    __syncthreads();
    if (tid == 0) {
        int f = atomicAdd(&g_barcnt[1], 1) + 1;
        if (f == 20) { g_barcnt[0] = 0; g_barcnt[1] = 0; __threadfence(); }
    }
}

__global__ void k_scatter(const int* __restrict__ ei) {
    int e = blockIdx.x * 256 + threadIdx.x;
    if (e < EE) {
        int s = edge_src(ei, e);
        int d = edge_dst(ei, e);
        if ((unsigned)s < NN && (unsigned)d < NN) {
            int pos = atomicAdd(&g_cursor[d], 1);
            int idx = g_rowptr[d] + pos;
            if ((unsigned)idx < EE) g_csr[idx] = s;
        }
    }
}

// ----------------------------- fused agg + GEMM (RT=64, prefetched gather) ---
template <int DOUT>
__global__ void __launch_bounds__(256) k_aggpre(
    const float* __restrict__ Uin, const float* __restrict__ Vin,
    const float* __restrict__ Wl, const float* __restrict__ Wr,
    const float* __restrict__ bl,
    float* __restrict__ Uout, float* __restrict__ Vout) {
    const int RT = 64, XS = 68;
    __shared__ float sX[RT][XS];
    __shared__ unsigned long long sW[32][DOUT + 2];
    int tid = threadIdx.x;
    int lane = tid & 31, wrp = tid >> 5;
    int n0 = blockIdx.x * RT;
    const float4* Uv = (const float4*)Uin;
    int sub = lane & 15, grp = lane >> 4;

    for (int i = 0; i < 8; i++) {
        int r = wrp * 8 + i;
        int node = n0 + r;
        if (node >= NN) {
            if (grp == 0) *(float4*)&sX[r][sub * 4] = make_float4(0.f, 0.f, 0.f, 0.f);
            continue;
        }
        int a = g_rowptr[node], b = g_rowptr[node + 1];
        int deg = b - a;
        float inv = 1.0f / (float)(deg > 0 ? deg : 1);
        float4 s0 = make_float4(0.f, 0.f, 0.f, 0.f), s1 = s0, s2 = s0, s3 = s0;
        int t = a + grp;
        // software-prefetched batched gather (batch 4, stride 2)
        int i0 = 0, i1 = 0, i2 = 0, i3 = 0;
        bool have = (t + 6 < b);
        if (have) { i0 = g_csr[t]; i1 = g_csr[t + 2]; i2 = g_csr[t + 4]; i3 = g_csr[t + 6]; }
        while (have) {
            int tn = t + 8;
            bool haven = (tn + 6 < b);
            int p0 = 0, p1 = 0, p2 = 0, p3 = 0;
            if (haven) { p0 = g_csr[tn]; p1 = g_csr[tn + 2]; p2 = g_csr[tn + 4]; p3 = g_csr[tn + 6]; }
            float4 v0 = __ldg(&Uv[(size_t)i0 * 16 + sub]);
            float4 v1 = __ldg(&Uv[(size_t)i1 * 16 + sub]);
            float4 v2 = __ldg(&Uv[(size_t)i2 * 16 + sub]);
            float4 v3 = __ldg(&Uv[(size_t)i3 * 16 + sub]);
            s0.x += v0.x; s0.y += v0.y; s0.z += v0.z; s0.w += v0.w;
            s1.x += v1.x; s1.y += v1.y; s1.z += v1.z; s1.w += v1.w;
            s2.x += v2.x; s2.y += v2.y; s2.z += v2.z; s2.w += v2.w;
            s3.x += v3.x; s3.y += v3.y; s3.z += v3.z; s3.w += v3.w;
            t = tn; i0 = p0; i1 = p1; i2 = p2; i3 = p3; have = haven;
        }
        for (; t < b; t += 2) {
            float4 v0 = __ldg(&Uv[(size_t)g_csr[t] * 16 + sub]);
            s0.x += v0.x; s0.y += v0.y; s0.z += v0.z; s0.w += v0.w;
        }
        float4 acc;
        acc.x = s0.x + s1.x + s2.x + s3.x;
        acc.y = s0.y + s1.y + s2.y + s3.y;
        acc.z = s0.z + s1.z + s2.z + s3.z;
        acc.w = s0.w + s1.w + s2.w + s3.w;
        acc.x += __shfl_xor_sync(0xffffffffu, acc.x, 16);
        acc.y += __shfl_xor_sync(0xffffffffu, acc.y, 16);
        acc.z += __shfl_xor_sync(0xffffffffu, acc.z, 16);
        acc.w += __shfl_xor_sync(0xffffffffu, acc.w, 16);
        if (grp == 0) {
            float4 vv = __ldg(&((const float4*)Vin)[(size_t)node * 16 + sub]);
            *(float4*)&sX[r][sub * 4] = make_float4(
                acc.x * inv + vv.x, acc.y * inv + vv.y,
                acc.z * inv + vv.z, acc.w * inv + vv.w);
        }
    }
    __syncthreads();
    gemm_from_smem<64, DOUT, RT, XS>(sX, sW, Wl, Wr, bl, Uout, Vout, n0, tid);
}

// ----------------------------- plain agg + add (prefetched gather) -----------
template <int D>
__global__ void k_aggadd(const float* __restrict__ U, const float* __restrict__ V,
                         float* __restrict__ out) {
    const int LPR = D / 4;
    const int G = 32 / LPR;
    int node = blockIdx.x * 8 + (threadIdx.x >> 5);
    int lane = threadIdx.x & 31;
    if (node >= NN) return;
    int sub = lane % LPR, grp = lane / LPR;
    int a = g_rowptr[node], b = g_rowptr[node + 1];
    int deg = b - a;
    float inv = 1.0f / (float)(deg > 0 ? deg : 1);
    const float4* Uv = (const float4*)U;

    float4 s0 = make_float4(0.f, 0.f, 0.f, 0.f), s1 = s0, s2 = s0, s3 = s0;
    int t = a + grp;
    int i0 = 0, i1 = 0, i2 = 0, i3 = 0;
    bool have = (t + 3 * G < b);
    if (have) { i0 = g_csr[t]; i1 = g_csr[t + G]; i2 = g_csr[t + 2 * G]; i3 = g_csr[t + 3 * G]; }
    while (have) {
        int tn = t + 4 * G;
        bool haven = (tn + 3 * G < b);
        int p0 = 0, p1 = 0, p2 = 0, p3 = 0;
        if (haven) { p0 = g_csr[tn]; p1 = g_csr[tn + G]; p2 = g_csr[tn + 2 * G]; p3 = g_csr[tn + 3 * G]; }
        float4 v0 = __ldg(&Uv[(size_t)i0 * LPR + sub]);
        float4 v1 = __ldg(&Uv[(size_t)i1 * LPR + sub]);
        float4 v2 = __ldg(&Uv[(size_t)i2 * LPR + sub]);
        float4 v3 = __ldg(&Uv[(size_t)i3 * LPR + sub]);
        s0.x += v0.x; s0.y += v0.y; s0.z += v0.z; s0.w += v0.w;
        s1.x += v1.x; s1.y += v1.y; s1.z += v1.z; s1.w += v1.w;
        s2.x += v2.x; s2.y += v2.y; s2.z += v2.z; s2.w += v2.w;
        s3.x += v3.x; s3.y += v3.y; s3.z += v3.z; s3.w += v3.w;
        t = tn; i0 = p0; i1 = p1; i2 = p2; i3 = p3; have = haven;
    }
    for (; t < b; t += G) {
        float4 v0 = __ldg(&Uv[(size_t)g_csr[t] * LPR + sub]);
        s0.x += v0.x; s0.y += v0.y; s0.z += v0.z; s0.w += v0.w;
    }
    float4 acc;
    acc.x = s0.x + s1.x + s2.x + s3.x;
    acc.y = s0.y + s1.y + s2.y + s3.y;
    acc.z = s0.z + s1.z + s2.z + s3.z;
    acc.w = s0.w + s1.w + s2.w + s3.w;
    #pragma unroll
    for (int off = LPR; off < 32; off <<= 1) {
        acc.x += __shfl_xor_sync(0xffffffffu, acc.x, off);
        acc.y += __shfl_xor_sync(0xffffffffu, acc.y, off);
        acc.z += __shfl_xor_sync(0xffffffffu, acc.z, off);
        acc.w += __shfl_xor_sync(0xffffffffu, acc.w, off);
    }
    if (grp == 0) {
        float4 vv = __ldg(&((const float4*)V)[(size_t)node * LPR + sub]);
        float4 res;
        res.x = acc.x * inv + vv.x;
        res.y = acc.y * inv + vv.y;
        res.z = acc.z * inv + vv.z;
        res.w = acc.w * inv + vv.w;
        ((float4*)out)[(size_t)node * LPR + sub] = res;
    }
}

// ----------------------------- conv composition precompute -------------------
__global__ void k_T(const float* __restrict__ Wc1, const float* __restrict__ Wc2,
                    const float* __restrict__ bc1) {
    int m = threadIdx.x;
    int d1 = blockIdx.x / 9, d0 = blockIdx.x % 9;
    float s = 0.f;
    for (int c = 0; c < 64; c++)
        s += Wc2[(m * 64 + c) * 9 + d1] * Wc1[c * 9 + d0];
    g_T[(d1 * 9 + d0) * 64 + m] = s;
    if (d0 == 0) {
        float sb = 0.f;
        for (int c = 0; c < 64; c++)
            sb += Wc2[(m * 64 + c) * 9 + d1] * bc1[c];
        g_Tb[d1 * 64 + m] = sb;
    }
}

__device__ __forceinline__ bool m1(int rc, int d) {
    if (rc == 0) return d >= 0;
    if (rc == 4) return d <= 0;
    return true;
}
__device__ __forceinline__ bool m2(int rc, int s) {
    if (rc == 0) return s >= 0;
    if (rc == 1) return s >= -1;
    if (rc == 3) return s <= 1;
    if (rc == 4) return s <= 0;
    return true;
}

__global__ void k_G(const float* __restrict__ Wc3, const float* __restrict__ bc2,
                    const float* __restrict__ bc3) {
    int cs = blockIdx.x;
    int rc = cs / 5, cc = cs % 5;
    int t = threadIdx.x;
    if (t < 49) {
        int Dr = t / 7 - 3, Dc = t % 7 - 3;
        float acc = 0.f;
        for (int d2 = 0; d2 < 9; d2++) {
            int d2r = d2 / 3 - 1, d2c = d2 % 3 - 1;
            if (!m1(rc, d2r) || !m1(cc, d2c)) continue;
            for (int d1 = 0; d1 < 9; d1++) {
                int d1r = d1 / 3 - 1, d1c = d1 % 3 - 1;
                if (!m2(rc, d2r + d1r) || !m2(cc, d2c + d1c)) continue;
                int d0r = Dr - d2r - d1r, d0c = Dc - d2c - d1c;
                if (d0r < -1 || d0r > 1 || d0c < -1 || d0c > 1) continue;
                int d0 = (d0r + 1) * 3 + (d0c + 1);
                float s = 0.f;
                for (int m = 0; m < 64; m++)
                    s += Wc3[m * 9 + d2] * g_T[(d1 * 9 + d0) * 64 + m];
                acc += s;
            }
        }
        g_G[cs * 49 + t] = acc;
    }
    if (t == 49) {
        float acc = __ldg(&bc3[0]);
        for (int d2 = 0; d2 < 9; d2++) {
            int d2r = d2 / 3 - 1, d2c = d2 % 3 - 1;
            if (!m1(rc, d2r) || !m1(cc, d2c)) continue;
            for (int m = 0; m < 64; m++) acc += Wc3[m * 9 + d2] * bc2[m];
            for (int d1 = 0; d1 < 9; d1++) {
                int d1r = d1 / 3 - 1, d1c = d1 % 3 - 1;
                if (!m2(rc, d2r + d1r) || !m2(cc, d2c + d1c)) continue;
                for (int m = 0; m < 64; m++) acc += Wc3[m * 9 + d2] * g_Tb[d1 * 64 + m];
            }
        }
        g_Bias[cs] = acc;
    }
}

// ---------------- fused (composed-conv + residual + W2 linear) ---------------
__global__ void k_conv(const float* __restrict__ hin, float* __restrict__ out,
                       const float* __restrict__ W2, const float* __restrict__ b2) {
    __shared__ float sH[38][64];
    __shared__ float sG[25][49];
    __shared__ float sBias[25];
    __shared__ float sPre[64][33];
    __shared__ float sW[32][65];
    int tid = threadIdx.x;
    int n0 = blockIdx.x * 32;

    for (int id = tid; id < 38 * 64; id += 256) {
        int r = id >> 6, c = id & 63;
        int gr = n0 - 3 + r;
        sH[r][c] = (gr >= 0 && gr < NN) ? hin[(size_t)gr * 64 + c] : 0.f;
    }
    for (int id = tid; id < 25 * 49; id += 256) sG[id / 49][id % 49] = g_G[id];
    if (tid < 25) sBias[tid] = g_Bias[tid];
    __syncthreads();

    for (int id = tid; id < 32 * 64; id += 256) {
        int r = id >> 6, c = id & 63;
        int gi = n0 + r;
        int rc = (gi == 0) ? 0 : (gi == 1) ? 1 : (gi == NN - 2) ? 3 : (gi == NN - 1) ? 4 : 2;
        int cc = (c == 0) ? 0 : (c == 1) ? 1 : (c == 62) ? 3 : (c == 63) ? 4 : 2;
        const float* g = sG[rc * 5 + cc];
        float acc = sBias[rc * 5 + cc];
        #pragma unroll
        for (int dr = 0; dr < 7; dr++) {
            #pragma unroll
            for (int dc = 0; dc < 7; dc++) {
                int cj = c + dc - 3;
                if (cj >= 0 && cj < 64)
                    acc += g[dr * 7 + dc] * sH[r + dr][cj];
            }
        }
        acc += sH[r + 3][c];
        sPre[c][r] = acc;
    }
    __syncthreads();

    int o = tid % 64, rg = tid / 64;
    float acc[8];
    #pragma unroll
    for (int r = 0; r < 8; r++) acc[r] = 0.f;
    for (int kt = 0; kt < 64; kt += 32) {
        for (int id = tid; id < 32 * 64; id += 256) {
            int kk = id & 31, oo = id >> 5;
            sW[kk][oo] = W2[oo * 64 + kt + kk];
        }
        __syncthreads();
        #pragma unroll
        for (int k = 0; k < 32; k++) {
            float w = sW[k][o];
            #pragma unroll
            for (int r = 0; r < 8; r++)
                acc[r] += sPre[kt + k][rg * 8 + r] * w;
        }
        __syncthreads();
    }
    float bb = __ldg(&b2[o]);
    #pragma unroll
    for (int r = 0; r < 8; r++)
        out[(size_t)(n0 + rg * 8 + r) * 64 + o] = acc[r] + bb;
}

// ----------------------------- launch ----------------------------------------
extern "C" void kernel_launch(void* const* d_in, const int* in_sizes, int n_in,
                              void* d_out, int out_size) {
    const float* x   = (const float*)d_in[0];
    const int*   ei  = (const int*)d_in[1];
    const float* Wl1 = (const float*)d_in[2];
    const float* bl1 = (const float*)d_in[3];
    const float* Wr1 = (const float*)d_in[4];
    const float* Wl2 = (const float*)d_in[5];
    const float* bl2 = (const float*)d_in[6];
    const float* Wr2 = (const float*)d_in[7];
    const float* Wl3 = (const float*)d_in[8];
    const float* bl3 = (const float*)d_in[9];
    const float* Wr3 = (const float*)d_in[10];
    const float* Wc1 = (const float*)d_in[11];
    const float* bc1 = (const float*)d_in[12];
    const float* Wc2 = (const float*)d_in[13];
    const float* bc2 = (const float*)d_in[14];
    const float* Wc3 = (const float*)d_in[15];
    const float* bc3 = (const float*)d_in[16];
    const float* W2  = (const float*)d_in[17];
    const float* b2  = (const float*)d_in[18];
    float* out = (float*)d_out;

    float *pA, *pB, *pU, *pV;
    cudaGetSymbolAddress((void**)&pA, g_A);
    cudaGetSymbolAddress((void**)&pB, g_B);
    cudaGetSymbolAddress((void**)&pU, g_U);
    cudaGetSymbolAddress((void**)&pV, g_V);

    // forked-stream capture: s2 = CSR build, s3 = conv compose
    cudaStream_t s2, s3;
    cudaStreamCreateWithFlags(&s2, cudaStreamNonBlocking);
    cudaStreamCreateWithFlags(&s3, cudaStreamNonBlocking);
    cudaEvent_t eFork, eCsr, eCompose;
    cudaEventCreateWithFlags(&eFork, cudaEventDisableTiming);
    cudaEventCreateWithFlags(&eCsr, cudaEventDisableTiming);
    cudaEventCreateWithFlags(&eCompose, cudaEventDisableTiming);

    cudaEventRecord(eFork, 0);
    cudaStreamWaitEvent(s2, eFork, 0);
    cudaStreamWaitEvent(s3, eFork, 0);

    // s2: CSR pipeline (scanA+scanC fused)
    k_zero<<<79, 256, 0, s2>>>(ei);
    k_hist<<<(EE + 255) / 256, 256, 0, s2>>>(ei);
    k_scan2<<<20, 1024, 0, s2>>>();
    k_scatter<<<(EE + 255) / 256, 256, 0, s2>>>(ei);
    cudaEventRecord(eCsr, s2);

    // s3: conv composition
    k_T<<<81, 64, 0, s3>>>(Wc1, Wc2, bc1);
    k_G<<<25, 64, 0, s3>>>(Wc3, bc2, bc3);
    cudaEventRecord(eCompose, s3);

    // main stream: pre1 (x -> U,V) runs concurrently with CSR build
    k_pre<128, 64><<<313, 256>>>(x, Wl1, Wr1, bl1, pU, pV);

    cudaStreamWaitEvent(0, eCsr, 0);

    // sage2 fused (agg(U,V) -> h1, GEMM -> A,B)
    k_aggpre<64><<<313, 256>>>(pU, pV, Wl2, Wr2, bl2, pA, pB);
    // sage2 fused (A,B) -> (U,V)
    k_aggpre<64><<<313, 256>>>(pA, pB, Wl2, Wr2, bl2, pU, pV);
    // h3 = agg(U,V) -> A   (conv input = out_1)
    k_aggadd<64><<<2500, 256>>>(pU, pV, pA);

    cudaStreamWaitEvent(0, eCompose, 0);
    // composed conv + residual + W2 linear: A -> B
    k_conv<<<625, 256>>>(pA, pB, W2, b2);

    // pre (B -> U,V)
    k_pre<64, 64><<<313, 256>>>(pB, Wl2, Wr2, bl2, pU, pV);
    // sage2 fused (U,V) -> (A,B)
    k_aggpre<64><<<313, 256>>>(pU, pV, Wl2, Wr2, bl2, pA, pB);
    // sage3 fused (A,B) -> (U,V)  (DOUT=32)
    k_aggpre<32><<<313, 256>>>(pA, pB, Wl3, Wr3, bl3, pU, pV);
    // out = agg(U,V) (32-dim)
    k_aggadd<32><<<2500, 256>>>(pU, pV, out);

    cudaEventDestroy(eFork);
    cudaEventDestroy(eCsr);
    cudaEventDestroy(eCompose);
    cudaStreamDestroy(s2);
    cudaStreamDestroy(s3);
}